// round 15
// baseline (speedup 1.0000x reference)
#include <cuda_runtime.h>
#include <cstdint>
#include <math.h>

#define BB   2
#define SS   2048
#define HHID 2048
#define NHQ  16
#define NKVH 4
#define DDIM 128
#define TTOK (BB*SS)     // 4096
#define PAD_ROWS 4224    // 33 tiles of 128

// ---------------- scratch (~58MB, proven-safe) ----------------
__device__ __align__(16) int g_src[PAD_ROWS];   // sorted row -> src token (-1 = pad)
__device__ unsigned g_tiles0_dev;
__device__ __align__(16) float g_q [(size_t)BB*NHQ *SS*DDIM];   // [B][NH][S][D]  (post-RoPE)
__device__ __align__(16) float g_k [(size_t)BB*NKVH*SS*DDIM];   // [B][NKV][S][D] (post-RoPE)
__device__ __align__(16) float g_v [(size_t)BB*NKVH*SS*DDIM];
__device__ __align__(16) float g_ao[(size_t)TTOK*HHID];         // [B][S][NH*D] token order

// ---------------- cp.async helpers ----------------
__device__ __forceinline__ uint32_t smem_u32(const void* p) {
    uint32_t a;
    asm("{ .reg .u64 t; cvta.to.shared.u64 t, %1; cvt.u32.u64 %0, t; }" : "=r"(a) : "l"(p));
    return a;
}
__device__ __forceinline__ void cp16(uint32_t d, const void* s) {
    uint64_t gs;
    asm("cvta.to.global.u64 %0, %1;" : "=l"(gs) : "l"(s));
    asm volatile("cp.async.cg.shared.global [%0], [%1], 16;" :: "r"(d), "l"(gs) : "memory");
}
#define CP_COMMIT() asm volatile("cp.async.commit_group;" ::: "memory")
#define CP_WAIT1()  asm volatile("cp.async.wait_group 1;" ::: "memory")
#define CP_WAIT0()  asm volatile("cp.async.wait_group 0;" ::: "memory")

// GEMM dyn smem layout: As[2][128][36] fp32 (row-major, 144B rows), Bs[2][32][128] fp32
#define A_STRF  36
#define A_STG   18432
#define OFF_B   (2*A_STG)            // 36864
#define B_STG   16384
#define SMEM_G  (OFF_B + 2*B_STG)    // 69632

// ===================== kernel: expert scan / permutation (proven) =====================
__global__ __launch_bounds__(1024) void scan_kernel(const int* __restrict__ tt)
{
    __shared__ int wtot[32];
    int tid = threadIdx.x, lane = tid & 31, wid = tid >> 5;
    for (int j = tid; j < PAD_ROWS; j += 1024) g_src[j] = -1;
    __syncthreads();

    int t0 = tid * 4;
    int cs[4];
#pragma unroll
    for (int i = 0; i < 4; i++) cs[i] = tt[t0 + i];
    int loc = cs[0] + cs[1] + cs[2] + cs[3];
    int inc = loc;
#pragma unroll
    for (int o = 1; o < 32; o <<= 1) { int v = __shfl_up_sync(0xffffffffu, inc, o); if (lane >= o) inc += v; }
    if (lane == 31) wtot[wid] = inc;
    __syncthreads();
    if (wid == 0) {
        int v = wtot[lane];
#pragma unroll
        for (int o = 1; o < 32; o <<= 1) { int u = __shfl_up_sync(0xffffffffu, v, o); if (lane >= o) v += u; }
        wtot[lane] = v;
    }
    __syncthreads();
    int total1 = wtot[31];
    int base1  = (wid > 0 ? wtot[wid - 1] : 0) + (inc - loc);
    int n0 = TTOK - total1;
    int tiles0 = (n0 + 127) >> 7;
    if (tid == 0) g_tiles0_dev = (unsigned)tiles0;
    int off1 = tiles0 * 128;
    int run1 = base1;
#pragma unroll
    for (int i = 0; i < 4; i++) {
        int idx = t0 + i;
        int dst = cs[i] ? (off1 + run1) : (idx - run1);
        g_src[dst] = idx;
        run1 += cs[i];
    }
}

// ===================== GEMM pieces (k-tile 32; A+B cp.async double-buffered) =====================
// Per-thread A-cp assignment: 4 granules, id = tid + it*256 -> row = id>>3, g = id&7
__device__ __forceinline__ void issue_stage(uint32_t aBase, uint32_t bBase,
    const float* __restrict__ A, const int* arows_src, const int* arow_idx, const int* ag_idx,
    const float* __restrict__ W, int nstr, int n0, int k0, int tid)
{
#pragma unroll
    for (int it = 0; it < 4; it++) {
        int src = arows_src[it];
        if (src >= 0) {
            cp16(aBase + (uint32_t)(arow_idx[it] * 144 + ag_idx[it] * 16),
                 &A[(size_t)src * 2048 + k0 + ag_idx[it] * 4]);
        }
    }
#pragma unroll
    for (int it = 0; it < 4; it++) {
        int f = tid + it * 256;
        int kr = f >> 5, nc = f & 31;
        cp16(bBase + (uint32_t)(kr * 128 + nc * 4) * 4,
             &W[(size_t)(k0 + kr) * nstr + n0 + nc * 4]);
    }
    CP_COMMIT();
}

__device__ __forceinline__ void gemm_compute(
    const float* __restrict__ As, const float (*Bs)[128], int tx, int ty, float acc[8][8])
{
#pragma unroll
    for (int k4 = 0; k4 < 8; k4++) {
#pragma unroll
        for (int h = 0; h < 2; h++) {
            float4 a4[4];
#pragma unroll
            for (int i = 0; i < 4; i++)
                a4[i] = *(const float4*)&As[(ty * 8 + h * 4 + i) * A_STRF + k4 * 4];
#pragma unroll
            for (int j4 = 0; j4 < 4; j4++) {
                float b[8];
                *(float4*)&b[0] = *(const float4*)&Bs[k4 * 4 + j4][tx * 8];
                *(float4*)&b[4] = *(const float4*)&Bs[k4 * 4 + j4][tx * 8 + 4];
#pragma unroll
                for (int i = 0; i < 4; i++) {
                    float av = (j4 == 0) ? a4[i].x : (j4 == 1) ? a4[i].y : (j4 == 2) ? a4[i].z : a4[i].w;
#pragma unroll
                    for (int j = 0; j < 8; j++)
                        acc[h * 4 + i][j] = fmaf(av, b[j], acc[h * 4 + i][j]);
                }
            }
        }
    }
}

__device__ __forceinline__ void gemm_mainloop(char* smem,
    const float* __restrict__ A, int m0,
    const float* __restrict__ W, int nstr, int n0, int tid, int tx, int ty,
    float acc[8][8])
{
    uint32_t aBase = smem_u32(smem);
    uint32_t bBase = smem_u32(smem + OFF_B);

    int arow_idx[4], ag_idx[4], arows_src[4];
#pragma unroll
    for (int it = 0; it < 4; it++) {
        int id = tid + it * 256;
        arow_idx[it] = id >> 3;
        ag_idx[it]   = id & 7;
        arows_src[it] = g_src[m0 + arow_idx[it]];
    }
    // zero pad-row granules ONCE in both stages (cp never issued for them)
#pragma unroll
    for (int it = 0; it < 4; it++) {
        if (arows_src[it] < 0) {
            float4 z = make_float4(0.f, 0.f, 0.f, 0.f);
            *(float4*)(smem + arow_idx[it] * 144 + ag_idx[it] * 16)         = z;
            *(float4*)(smem + A_STG + arow_idx[it] * 144 + ag_idx[it] * 16) = z;
        }
    }

    issue_stage(aBase, bBase, A, arows_src, arow_idx, ag_idx, W, nstr, n0, 0, tid);

    for (int s = 0; s < 64; s++) {
        __syncthreads();                 // compute s-1 done: buf (s+1)&1 free
        if (s + 1 < 64) {
            issue_stage(aBase + ((s + 1) & 1) * A_STG, bBase + ((s + 1) & 1) * B_STG,
                        A, arows_src, arow_idx, ag_idx, W, nstr, n0, (s + 1) * 32, tid);
            CP_WAIT1();                  // stage s complete
        } else {
            CP_WAIT0();
        }
        __syncthreads();                 // stage s visible to all
        gemm_compute((const float*)(smem + (s & 1) * A_STG),
                     (const float(*)[128])(smem + OFF_B + (s & 1) * B_STG), tx, ty, acc);
    }
}

// ===================== kernel: QKV projection + bias + RoPE =====================
// grid (33, 24). block 256. dyn smem SMEM_G.
__global__ __launch_bounds__(256, 2) void qkv_kernel(
    const float* __restrict__ hs,
    const float* __restrict__ Wq, const float* __restrict__ bq,
    const float* __restrict__ Wk, const float* __restrict__ bk,
    const float* __restrict__ Wv, const float* __restrict__ bv,
    const float* __restrict__ cosp, const float* __restrict__ sinp)
{
    extern __shared__ char smq[];
    const int rt = blockIdx.x, ct = blockIdx.y;
    const int tiles0 = (int)g_tiles0_dev;
    const int e = (rt < tiles0) ? 0 : 1;
    const int m0 = rt * 128;

    const float* W; const float* bias; int nstr, n0, which, head;
    if (ct < 16)      { W = Wq; bias = bq; nstr = 2048; n0 = ct * 128;        which = 0; head = ct;      }
    else if (ct < 20) { W = Wk; bias = bk; nstr = 512;  n0 = (ct - 16) * 128; which = 1; head = ct - 16; }
    else              { W = Wv; bias = bv; nstr = 512;  n0 = (ct - 20) * 128; which = 2; head = ct - 20; }
    W    += (size_t)e * 2048 * nstr;
    bias += (size_t)e * nstr;

    const int tid = threadIdx.x;
    const int tx = tid & 15, ty = tid >> 4;

    float acc[8][8];
#pragma unroll
    for (int i = 0; i < 8; i++)
#pragma unroll
        for (int j = 0; j < 8; j++) acc[i][j] = 0.f;

    gemm_mainloop(smq, hs, m0, W, nstr, n0, tid, tx, ty, acc);

    // ---- epilogue: bias + fused RoPE (shfl pair) + scatter ----
    const float* bp = bias + n0;
#pragma unroll
    for (int i = 0; i < 8; i++) {
        const int row = m0 + ty * 8 + i;
        const int src = g_src[row];
        const int sEff = (src >= 0) ? src : 0;
        const int b = sEff >> 11, s = sEff & 2047;

        float v8[8];
#pragma unroll
        for (int j = 0; j < 8; j++) v8[j] = acc[i][j] + __ldg(&bp[tx * 8 + j]);

        if (which < 2) {
            float p8[8];
#pragma unroll
            for (int j = 0; j < 8; j++) p8[j] = __shfl_xor_sync(0xffffffffu, v8[j], 8);
            const size_t cb = ((size_t)(b * 2048 + s)) * 128;
#pragma unroll
            for (int j = 0; j < 8; j++) {
                int col = tx * 8 + j;
                float c  = __ldg(&cosp[cb + col]);
                float sn = __ldg(&sinp[cb + col]);
                v8[j] = (tx < 8) ? (v8[j] * c - p8[j] * sn)
                                 : (v8[j] * c + p8[j] * sn);
            }
        }

        if (src >= 0) {
            float* dst;
            if (which == 0)      dst = &g_q[((size_t)((b * NHQ  + head) * SS + s)) * DDIM + tx * 8];
            else if (which == 1) dst = &g_k[((size_t)((b * NKVH + head) * SS + s)) * DDIM + tx * 8];
            else                 dst = &g_v[((size_t)((b * NKVH + head) * SS + s)) * DDIM + tx * 8];
            *(float4*)&dst[0] = make_float4(v8[0], v8[1], v8[2], v8[3]);
            *(float4*)&dst[4] = make_float4(v8[4], v8[5], v8[6], v8[7]);
        }
    }
}

// ===================== kernel: causal flash attention (fp32 SIMT, K/V register prefetch) — R13 proven =====================
__global__ __launch_bounds__(256) void attn_kernel()
{
    extern __shared__ float sm[];
    float* sQt = sm;               // [128 d][128 r]
    float* sKt = sm + 16384;       // [128 d][64 c]
    float* sV  = sm + 24576;       // [64 c][128 d]
    float* sPt = sm + 32768;       // [64 c][128 r]

    const int bh = blockIdx.y;
    const int b = bh >> 4, h = bh & 15, hk = h >> 2;
    const int qt = 15 - blockIdx.x;
    const int q0 = qt * 128;
    const float* Q = g_q + (size_t)(b * NHQ  + h ) * SS * DDIM;
    const float* K = g_k + (size_t)(b * NKVH + hk) * SS * DDIM;
    const float* V = g_v + (size_t)(b * NKVH + hk) * SS * DDIM;

    const int tid = threadIdx.x;
    const int tx = tid & 15, ty = tid >> 4;

#pragma unroll
    for (int it = 0; it < 16; it++) {
        int f = tid + it * 256;
        int r = f >> 5, dc = f & 31;
        float4 v = *(const float4*)&Q[(size_t)(q0 + r) * DDIM + dc * 4];
        sQt[(dc * 4 + 0) * 128 + r] = v.x;
        sQt[(dc * 4 + 1) * 128 + r] = v.y;
        sQt[(dc * 4 + 2) * 128 + r] = v.z;
        sQt[(dc * 4 + 3) * 128 + r] = v.w;
    }

    float accO[8][8];
    float mrow[8], lrow[8];
#pragma unroll
    for (int i = 0; i < 8; i++) {
        mrow[i] = -1e30f; lrow[i] = 0.f;
#pragma unroll
        for (int j = 0; j < 8; j++) accO[i][j] = 0.f;
    }

    const float scale = 0.08838834764831845f;
    const int ktiles = 2 * qt + 2;

    float4 kreg[8], vreg[8];
    {
#pragma unroll
        for (int it = 0; it < 8; it++) {
            int f = tid + it * 256;
            int c = f >> 5, dc = f & 31;
            kreg[it] = *(const float4*)&K[(size_t)c * DDIM + dc * 4];
            vreg[it] = *(const float4*)&V[(size_t)c * DDIM + dc * 4];
        }
    }

    for (int kt = 0; kt < ktiles; kt++) {
        __syncthreads();
#pragma unroll
        for (int it = 0; it < 8; it++) {
            int f = tid + it * 256;
            int c = f >> 5, dc = f & 31;
            sKt[(dc * 4 + 0) * 64 + c] = kreg[it].x;
            sKt[(dc * 4 + 1) * 64 + c] = kreg[it].y;
            sKt[(dc * 4 + 2) * 64 + c] = kreg[it].z;
            sKt[(dc * 4 + 3) * 64 + c] = kreg[it].w;
            *(float4*)&sV[c * 128 + dc * 4] = vreg[it];
        }
        __syncthreads();
        if (kt + 1 < ktiles) {
            const int kn = (kt + 1) * 64;
#pragma unroll
            for (int it = 0; it < 8; it++) {
                int f = tid + it * 256;
                int c = f >> 5, dc = f & 31;
                kreg[it] = *(const float4*)&K[(size_t)(kn + c) * DDIM + dc * 4];
                vreg[it] = *(const float4*)&V[(size_t)(kn + c) * DDIM + dc * 4];
            }
        }

        const int k0 = kt * 64;
        float sc[8][4];
#pragma unroll
        for (int i = 0; i < 8; i++)
#pragma unroll
            for (int j = 0; j < 4; j++) sc[i][j] = 0.f;
#pragma unroll 8
        for (int d = 0; d < 128; d++) {
            float qf[8], kf[4];
            *(float4*)&qf[0] = *(float4*)&sQt[d * 128 + ty * 8];
            *(float4*)&qf[4] = *(float4*)&sQt[d * 128 + ty * 8 + 4];
            *(float4*)&kf[0] = *(float4*)&sKt[d * 64 + tx * 4];
#pragma unroll
            for (int i = 0; i < 8; i++)
#pragma unroll
                for (int j = 0; j < 4; j++)
                    sc[i][j] = fmaf(qf[i], kf[j], sc[i][j]);
        }
#pragma unroll
        for (int i = 0; i < 8; i++)
#pragma unroll
            for (int j = 0; j < 4; j++) sc[i][j] *= scale;
        if (k0 + 63 > q0) {
#pragma unroll
            for (int i = 0; i < 8; i++)
#pragma unroll
                for (int j = 0; j < 4; j++)
                    if (k0 + tx * 4 + j > q0 + ty * 8 + i) sc[i][j] = -1e30f;
        }
#pragma unroll
        for (int i = 0; i < 8; i++) {
            float mx = fmaxf(fmaxf(sc[i][0], sc[i][1]), fmaxf(sc[i][2], sc[i][3]));
#pragma unroll
            for (int o = 1; o < 16; o <<= 1) mx = fmaxf(mx, __shfl_xor_sync(0xffffffffu, mx, o));
            float mn = fmaxf(mrow[i], mx);
            float alpha = __expf(mrow[i] - mn);
            mrow[i] = mn;
            float rs = 0.f;
#pragma unroll
            for (int j = 0; j < 4; j++) { float p = __expf(sc[i][j] - mn); sc[i][j] = p; rs += p; }
#pragma unroll
            for (int o = 1; o < 16; o <<= 1) rs += __shfl_xor_sync(0xffffffffu, rs, o);
            lrow[i] = lrow[i] * alpha + rs;
#pragma unroll
            for (int j = 0; j < 8; j++) accO[i][j] *= alpha;
        }
#pragma unroll
        for (int i = 0; i < 8; i++)
#pragma unroll
            for (int j = 0; j < 4; j++)
                sPt[(tx * 4 + j) * 128 + ty * 8 + i] = sc[i][j];
        __syncthreads();
#pragma unroll 4
        for (int c = 0; c < 64; c++) {
            float pf[8], vf[8];
            *(float4*)&pf[0] = *(float4*)&sPt[c * 128 + ty * 8];
            *(float4*)&pf[4] = *(float4*)&sPt[c * 128 + ty * 8 + 4];
            *(float4*)&vf[0] = *(float4*)&sV[c * 128 + tx * 8];
            *(float4*)&vf[4] = *(float4*)&sV[c * 128 + tx * 8 + 4];
#pragma unroll
            for (int i = 0; i < 8; i++)
#pragma unroll
                for (int j = 0; j < 8; j++)
                    accO[i][j] = fmaf(pf[i], vf[j], accO[i][j]);
        }
    }

#pragma unroll
    for (int i = 0; i < 8; i++) {
        float inv = 1.f / lrow[i];
        int srow = q0 + ty * 8 + i;
        float* dst = &g_ao[(size_t)(b * SS + srow) * HHID + h * DDIM + tx * 8];
        *(float4*)&dst[0] = make_float4(accO[i][0] * inv, accO[i][1] * inv, accO[i][2] * inv, accO[i][3] * inv);
        *(float4*)&dst[4] = make_float4(accO[i][4] * inv, accO[i][5] * inv, accO[i][6] * inv, accO[i][7] * inv);
    }
}

// ===================== kernel: O projection (A+B cp.async double-buffer) =====================
// grid (33, 16). block 256. dyn smem SMEM_G.
__global__ __launch_bounds__(256, 2) void oproj_kernel(
    const float* __restrict__ Wo, float* __restrict__ out)
{
    extern __shared__ char smo[];
    const int rt = blockIdx.x, ct = blockIdx.y;
    const int tiles0 = (int)g_tiles0_dev;
    const int e = (rt < tiles0) ? 0 : 1;
    const int m0 = rt * 128, n0 = ct * 128;
    const float* W = Wo + (size_t)e * 2048 * 2048;

    const int tid = threadIdx.x;
    const int tx = tid & 15, ty = tid >> 4;

    float acc[8][8];
#pragma unroll
    for (int i = 0; i < 8; i++)
#pragma unroll
        for (int j = 0; j < 8; j++) acc[i][j] = 0.f;

    gemm_mainloop(smo, g_ao, m0, W, 2048, n0, tid, tx, ty, acc);

#pragma unroll
    for (int i = 0; i < 8; i++) {
        const int src = g_src[m0 + ty * 8 + i];
        if (src >= 0) {
            float* dst = &out[(size_t)src * 2048 + n0 + tx * 8];
            *(float4*)&dst[0] = make_float4(acc[i][0], acc[i][1], acc[i][2], acc[i][3]);
            *(float4*)&dst[4] = make_float4(acc[i][4], acc[i][5], acc[i][6], acc[i][7]);
        }
    }
}

// =====================================================================
extern "C" void kernel_launch(void* const* d_in, const int* in_sizes, int n_in,
                              void* d_out, int out_size)
{
    const float* hs   = (const float*)d_in[0];
    const int*   tt   = (const int*)  d_in[1];
    const float* cosp = (const float*)d_in[2];
    const float* sinp = (const float*)d_in[3];
    const float* Wq   = (const float*)d_in[4];
    const float* bq   = (const float*)d_in[5];
    const float* Wk   = (const float*)d_in[6];
    const float* bk   = (const float*)d_in[7];
    const float* Wv   = (const float*)d_in[8];
    const float* bv   = (const float*)d_in[9];
    const float* Wo   = (const float*)d_in[10];
    float* out = (float*)d_out;

    cudaFuncSetAttribute(attn_kernel,  cudaFuncAttributeMaxDynamicSharedMemorySize, 163840);
    cudaFuncSetAttribute(qkv_kernel,   cudaFuncAttributeMaxDynamicSharedMemorySize, SMEM_G);
    cudaFuncSetAttribute(oproj_kernel, cudaFuncAttributeMaxDynamicSharedMemorySize, SMEM_G);

    scan_kernel<<<1, 1024>>>(tt);
    qkv_kernel<<<dim3(33, 24), 256, SMEM_G>>>(hs, Wq, bq, Wk, bk, Wv, bv, cosp, sinp);
    attn_kernel<<<dim3(16, 32), 256, 163840>>>();
    oproj_kernel<<<dim3(33, 16), 256, SMEM_G>>>(Wo, out);
}

// round 16
// speedup vs baseline: 1.0764x; 1.0764x over previous
#include <cuda_runtime.h>
#include <cstdint>
#include <math.h>

#define BB   2
#define SS   2048
#define HHID 2048
#define NHQ  16
#define NKVH 4
#define DDIM 128
#define TTOK (BB*SS)     // 4096
#define PAD_ROWS 4224    // 33 tiles of 128

// ---------------- scratch (~85MB, proven-safe envelope) ----------------
__device__ __align__(16) int g_src[PAD_ROWS];   // sorted row -> src token (-1 = pad)
__device__ __align__(16) int g_dst[TTOK];       // src token -> sorted row
__device__ unsigned g_tiles0_dev;
__device__ __align__(16) float g_q [(size_t)BB*NHQ *SS*DDIM];   // [B][NH][S][D]  (post-RoPE)
__device__ __align__(16) float g_k [(size_t)BB*NKVH*SS*DDIM];   // [B][NKV][S][D] (post-RoPE)
__device__ __align__(16) float g_v [(size_t)BB*NKVH*SS*DDIM];
// Transposed activation buffer, ALIASED:
//   phase 1 (gatherT -> qkv):   g_xT[k][m] = gathered hs (pads zero)
//   phase 2 (attn -> oproj):    g_xT[k][m] = attention output (sorted cols, pads stay zero)
__device__ __align__(16) float g_xT[(size_t)HHID*PAD_ROWS];

// ---------------- cp.async helpers ----------------
__device__ __forceinline__ uint32_t smem_u32(const void* p) {
    uint32_t a;
    asm("{ .reg .u64 t; cvta.to.shared.u64 t, %1; cvt.u32.u64 %0, t; }" : "=r"(a) : "l"(p));
    return a;
}
__device__ __forceinline__ void cp16(uint32_t d, const void* s) {
    uint64_t gs;
    asm("cvta.to.global.u64 %0, %1;" : "=l"(gs) : "l"(s));
    asm volatile("cp.async.cg.shared.global [%0], [%1], 16;" :: "r"(d), "l"(gs) : "memory");
}
#define CP_COMMIT() asm volatile("cp.async.commit_group;" ::: "memory")
#define CP_WAIT1()  asm volatile("cp.async.wait_group 1;" ::: "memory")
#define CP_WAIT0()  asm volatile("cp.async.wait_group 0;" ::: "memory")

// GEMM dyn smem: As[2][32][132] fp32, Bs[2][32][128] fp32
#define A_STG   16896
#define OFF_B   (2*A_STG)            // 33792
#define B_STG   16384
#define SMEM_G  (OFF_B + 2*B_STG)    // 66560

// ===================== kernel: expert scan / permutation =====================
__global__ __launch_bounds__(1024) void scan_kernel(const int* __restrict__ tt)
{
    __shared__ int wtot[32];
    int tid = threadIdx.x, lane = tid & 31, wid = tid >> 5;
    for (int j = tid; j < PAD_ROWS; j += 1024) g_src[j] = -1;
    __syncthreads();

    int t0 = tid * 4;
    int cs[4];
#pragma unroll
    for (int i = 0; i < 4; i++) cs[i] = tt[t0 + i];
    int loc = cs[0] + cs[1] + cs[2] + cs[3];
    int inc = loc;
#pragma unroll
    for (int o = 1; o < 32; o <<= 1) { int v = __shfl_up_sync(0xffffffffu, inc, o); if (lane >= o) inc += v; }
    if (lane == 31) wtot[wid] = inc;
    __syncthreads();
    if (wid == 0) {
        int v = wtot[lane];
#pragma unroll
        for (int o = 1; o < 32; o <<= 1) { int u = __shfl_up_sync(0xffffffffu, v, o); if (lane >= o) v += u; }
        wtot[lane] = v;
    }
    __syncthreads();
    int total1 = wtot[31];
    int base1  = (wid > 0 ? wtot[wid - 1] : 0) + (inc - loc);
    int n0 = TTOK - total1;
    int tiles0 = (n0 + 127) >> 7;
    if (tid == 0) g_tiles0_dev = (unsigned)tiles0;
    int off1 = tiles0 * 128;
    int run1 = base1;
#pragma unroll
    for (int i = 0; i < 4; i++) {
        int idx = t0 + i;
        int dst = cs[i] ? (off1 + run1) : (idx - run1);
        g_dst[idx] = dst;
        g_src[dst] = idx;
        run1 += cs[i];
    }
}

// ===================== kernel: gather + transpose hs -> g_xT (pads zero) =====================
// grid (132, 64), block (32, 8)
__global__ __launch_bounds__(256) void gatherT_kernel(const float* __restrict__ hs)
{
    __shared__ float t[32][33];
    const int m0 = blockIdx.x * 32, k0 = blockIdx.y * 32;
    const int tx = threadIdx.x, ty = threadIdx.y;
#pragma unroll
    for (int i = 0; i < 4; i++) {
        int r = ty + 8 * i;
        int src = g_src[m0 + r];
        t[r][tx] = (src >= 0) ? hs[(size_t)src * 2048 + k0 + tx] : 0.f;
    }
    __syncthreads();
#pragma unroll
    for (int i = 0; i < 4; i++) {
        int kk = ty + 8 * i;
        g_xT[(size_t)(k0 + kk) * PAD_ROWS + m0 + tx] = t[tx][kk];
    }
}

// ===================== GEMM (k-tile 32; A+B cp.async double-buffered, R14 compute) =====================
__device__ __forceinline__ void issue_stage(uint32_t aBase, uint32_t bBase,
    const float* __restrict__ AT, int m0,
    const float* __restrict__ W, int nstr, int n0, int k0, int tid)
{
#pragma unroll
    for (int it = 0; it < 4; it++) {
        int id = tid + it * 256;
        int kr = id >> 5, g = id & 31;
        cp16(aBase + (uint32_t)(kr * 132 + g * 4) * 4,
             &AT[(size_t)(k0 + kr) * PAD_ROWS + m0 + g * 4]);
    }
#pragma unroll
    for (int it = 0; it < 4; it++) {
        int f = tid + it * 256;
        int kr = f >> 5, nc = f & 31;
        cp16(bBase + (uint32_t)(kr * 128 + nc * 4) * 4,
             &W[(size_t)(k0 + kr) * nstr + n0 + nc * 4]);
    }
    CP_COMMIT();
}

__device__ __forceinline__ void gemm_compute(
    const float (*As)[132], const float (*Bs)[128], int tx, int ty, float acc[8][8])
{
#pragma unroll 8
    for (int kk = 0; kk < 32; kk++) {
        float a[8], b[8];
        *(float4*)&a[0] = *(const float4*)&As[kk][ty * 8];
        *(float4*)&a[4] = *(const float4*)&As[kk][ty * 8 + 4];
        *(float4*)&b[0] = *(const float4*)&Bs[kk][tx * 8];
        *(float4*)&b[4] = *(const float4*)&Bs[kk][tx * 8 + 4];
#pragma unroll
        for (int i = 0; i < 8; i++)
#pragma unroll
            for (int j = 0; j < 8; j++)
                acc[i][j] = fmaf(a[i], b[j], acc[i][j]);
    }
}

__device__ __forceinline__ void gemm_mainloop(char* smem,
    const float* __restrict__ AT, int m0,
    const float* __restrict__ W, int nstr, int n0, int tid, int tx, int ty,
    float acc[8][8])
{
    uint32_t aBase = smem_u32(smem);
    uint32_t bBase = smem_u32(smem + OFF_B);

    issue_stage(aBase, bBase, AT, m0, W, nstr, n0, 0, tid);

    for (int s = 0; s < 64; s++) {
        __syncthreads();                 // compute s-1 done: buf (s+1)&1 free
        if (s + 1 < 64) {
            issue_stage(aBase + ((s + 1) & 1) * A_STG, bBase + ((s + 1) & 1) * B_STG,
                        AT, m0, W, nstr, n0, (s + 1) * 32, tid);
            CP_WAIT1();                  // stage s complete
        } else {
            CP_WAIT0();
        }
        __syncthreads();                 // stage s visible
        gemm_compute((const float(*)[132])(smem + (s & 1) * A_STG),
                     (const float(*)[128])(smem + OFF_B + (s & 1) * B_STG), tx, ty, acc);
    }
}

// ===================== kernel: QKV projection + bias + RoPE =====================
// grid (33, 24). block 256. dyn smem SMEM_G.
__global__ __launch_bounds__(256, 2) void qkv_kernel(
    const float* __restrict__ Wq, const float* __restrict__ bq,
    const float* __restrict__ Wk, const float* __restrict__ bk,
    const float* __restrict__ Wv, const float* __restrict__ bv,
    const float* __restrict__ cosp, const float* __restrict__ sinp)
{
    extern __shared__ char smq[];
    const int rt = blockIdx.x, ct = blockIdx.y;
    const int tiles0 = (int)g_tiles0_dev;
    const int e = (rt < tiles0) ? 0 : 1;
    const int m0 = rt * 128;

    const float* W; const float* bias; int nstr, n0, which, head;
    if (ct < 16)      { W = Wq; bias = bq; nstr = 2048; n0 = ct * 128;        which = 0; head = ct;      }
    else if (ct < 20) { W = Wk; bias = bk; nstr = 512;  n0 = (ct - 16) * 128; which = 1; head = ct - 16; }
    else              { W = Wv; bias = bv; nstr = 512;  n0 = (ct - 20) * 128; which = 2; head = ct - 20; }
    W    += (size_t)e * 2048 * nstr;
    bias += (size_t)e * nstr;

    const int tid = threadIdx.x;
    const int tx = tid & 15, ty = tid >> 4;

    float acc[8][8];
#pragma unroll
    for (int i = 0; i < 8; i++)
#pragma unroll
        for (int j = 0; j < 8; j++) acc[i][j] = 0.f;

    gemm_mainloop(smq, g_xT, m0, W, nstr, n0, tid, tx, ty, acc);

    // ---- epilogue: bias + fused RoPE (shfl pair) + scatter ----
    const float* bp = bias + n0;
#pragma unroll
    for (int i = 0; i < 8; i++) {
        const int row = m0 + ty * 8 + i;
        const int src = g_src[row];
        const int sEff = (src >= 0) ? src : 0;
        const int b = sEff >> 11, s = sEff & 2047;

        float v8[8];
#pragma unroll
        for (int j = 0; j < 8; j++) v8[j] = acc[i][j] + __ldg(&bp[tx * 8 + j]);

        if (which < 2) {
            float p8[8];
#pragma unroll
            for (int j = 0; j < 8; j++) p8[j] = __shfl_xor_sync(0xffffffffu, v8[j], 8);
            const size_t cb = ((size_t)(b * 2048 + s)) * 128;
#pragma unroll
            for (int j = 0; j < 8; j++) {
                int col = tx * 8 + j;
                float c  = __ldg(&cosp[cb + col]);
                float sn = __ldg(&sinp[cb + col]);
                v8[j] = (tx < 8) ? (v8[j] * c - p8[j] * sn)
                                 : (v8[j] * c + p8[j] * sn);
            }
        }

        if (src >= 0) {
            float* dst;
            if (which == 0)      dst = &g_q[((size_t)((b * NHQ  + head) * SS + s)) * DDIM + tx * 8];
            else if (which == 1) dst = &g_k[((size_t)((b * NKVH + head) * SS + s)) * DDIM + tx * 8];
            else                 dst = &g_v[((size_t)((b * NKVH + head) * SS + s)) * DDIM + tx * 8];
            *(float4*)&dst[0] = make_float4(v8[0], v8[1], v8[2], v8[3]);
            *(float4*)&dst[4] = make_float4(v8[4], v8[5], v8[6], v8[7]);
        }
    }
}

// ===================== kernel: causal flash attention (R13 proven mainloop; transposed epilogue) =====================
__global__ __launch_bounds__(256) void attn_kernel()
{
    extern __shared__ float sm[];
    float* sQt = sm;               // [128 d][128 r]
    float* sKt = sm + 16384;       // [128 d][64 c]
    float* sV  = sm + 24576;       // [64 c][128 d]
    float* sPt = sm + 32768;       // [64 c][128 r]

    const int bh = blockIdx.y;
    const int b = bh >> 4, h = bh & 15, hk = h >> 2;
    const int qt = 15 - blockIdx.x;
    const int q0 = qt * 128;
    const float* Q = g_q + (size_t)(b * NHQ  + h ) * SS * DDIM;
    const float* K = g_k + (size_t)(b * NKVH + hk) * SS * DDIM;
    const float* V = g_v + (size_t)(b * NKVH + hk) * SS * DDIM;

    const int tid = threadIdx.x;
    const int tx = tid & 15, ty = tid >> 4;

#pragma unroll
    for (int it = 0; it < 16; it++) {
        int f = tid + it * 256;
        int r = f >> 5, dc = f & 31;
        float4 v = *(const float4*)&Q[(size_t)(q0 + r) * DDIM + dc * 4];
        sQt[(dc * 4 + 0) * 128 + r] = v.x;
        sQt[(dc * 4 + 1) * 128 + r] = v.y;
        sQt[(dc * 4 + 2) * 128 + r] = v.z;
        sQt[(dc * 4 + 3) * 128 + r] = v.w;
    }

    float accO[8][8];
    float mrow[8], lrow[8];
#pragma unroll
    for (int i = 0; i < 8; i++) {
        mrow[i] = -1e30f; lrow[i] = 0.f;
#pragma unroll
        for (int j = 0; j < 8; j++) accO[i][j] = 0.f;
    }

    const float scale = 0.08838834764831845f;
    const int ktiles = 2 * qt + 2;

    float4 kreg[8], vreg[8];
    {
#pragma unroll
        for (int it = 0; it < 8; it++) {
            int f = tid + it * 256;
            int c = f >> 5, dc = f & 31;
            kreg[it] = *(const float4*)&K[(size_t)c * DDIM + dc * 4];
            vreg[it] = *(const float4*)&V[(size_t)c * DDIM + dc * 4];
        }
    }

    for (int kt = 0; kt < ktiles; kt++) {
        __syncthreads();
#pragma unroll
        for (int it = 0; it < 8; it++) {
            int f = tid + it * 256;
            int c = f >> 5, dc = f & 31;
            sKt[(dc * 4 + 0) * 64 + c] = kreg[it].x;
            sKt[(dc * 4 + 1) * 64 + c] = kreg[it].y;
            sKt[(dc * 4 + 2) * 64 + c] = kreg[it].z;
            sKt[(dc * 4 + 3) * 64 + c] = kreg[it].w;
            *(float4*)&sV[c * 128 + dc * 4] = vreg[it];
        }
        __syncthreads();
        if (kt + 1 < ktiles) {
            const int kn = (kt + 1) * 64;
#pragma unroll
            for (int it = 0; it < 8; it++) {
                int f = tid + it * 256;
                int c = f >> 5, dc = f & 31;
                kreg[it] = *(const float4*)&K[(size_t)(kn + c) * DDIM + dc * 4];
                vreg[it] = *(const float4*)&V[(size_t)(kn + c) * DDIM + dc * 4];
            }
        }

        const int k0 = kt * 64;
        float sc[8][4];
#pragma unroll
        for (int i = 0; i < 8; i++)
#pragma unroll
            for (int j = 0; j < 4; j++) sc[i][j] = 0.f;
#pragma unroll 8
        for (int d = 0; d < 128; d++) {
            float qf[8], kf[4];
            *(float4*)&qf[0] = *(float4*)&sQt[d * 128 + ty * 8];
            *(float4*)&qf[4] = *(float4*)&sQt[d * 128 + ty * 8 + 4];
            *(float4*)&kf[0] = *(float4*)&sKt[d * 64 + tx * 4];
#pragma unroll
            for (int i = 0; i < 8; i++)
#pragma unroll
                for (int j = 0; j < 4; j++)
                    sc[i][j] = fmaf(qf[i], kf[j], sc[i][j]);
        }
#pragma unroll
        for (int i = 0; i < 8; i++)
#pragma unroll
            for (int j = 0; j < 4; j++) sc[i][j] *= scale;
        if (k0 + 63 > q0) {
#pragma unroll
            for (int i = 0; i < 8; i++)
#pragma unroll
                for (int j = 0; j < 4; j++)
                    if (k0 + tx * 4 + j > q0 + ty * 8 + i) sc[i][j] = -1e30f;
        }
#pragma unroll
        for (int i = 0; i < 8; i++) {
            float mx = fmaxf(fmaxf(sc[i][0], sc[i][1]), fmaxf(sc[i][2], sc[i][3]));
#pragma unroll
            for (int o = 1; o < 16; o <<= 1) mx = fmaxf(mx, __shfl_xor_sync(0xffffffffu, mx, o));
            float mn = fmaxf(mrow[i], mx);
            float alpha = __expf(mrow[i] - mn);
            mrow[i] = mn;
            float rs = 0.f;
#pragma unroll
            for (int j = 0; j < 4; j++) { float p = __expf(sc[i][j] - mn); sc[i][j] = p; rs += p; }
#pragma unroll
            for (int o = 1; o < 16; o <<= 1) rs += __shfl_xor_sync(0xffffffffu, rs, o);
            lrow[i] = lrow[i] * alpha + rs;
#pragma unroll
            for (int j = 0; j < 8; j++) accO[i][j] *= alpha;
        }
#pragma unroll
        for (int i = 0; i < 8; i++)
#pragma unroll
            for (int j = 0; j < 4; j++)
                sPt[(tx * 4 + j) * 128 + ty * 8 + i] = sc[i][j];
        __syncthreads();
#pragma unroll 4
        for (int c = 0; c < 64; c++) {
            float pf[8], vf[8];
            *(float4*)&pf[0] = *(float4*)&sPt[c * 128 + ty * 8];
            *(float4*)&pf[4] = *(float4*)&sPt[c * 128 + ty * 8 + 4];
            *(float4*)&vf[0] = *(float4*)&sV[c * 128 + tx * 8];
            *(float4*)&vf[4] = *(float4*)&sV[c * 128 + tx * 8 + 4];
#pragma unroll
            for (int i = 0; i < 8; i++)
#pragma unroll
                for (int j = 0; j < 8; j++)
                    accO[i][j] = fmaf(pf[i], vf[j], accO[i][j]);
        }
    }

    // ---- epilogue: normalize, write TRANSPOSED into g_xT[k][sorted_row] ----
#pragma unroll
    for (int i = 0; i < 8; i++) {
        float inv = 1.f / lrow[i];
        int srow = q0 + ty * 8 + i;
        int dstrow = g_dst[b * 2048 + srow];
#pragma unroll
        for (int j = 0; j < 8; j++) {
            int k = h * DDIM + tx * 8 + j;
            g_xT[(size_t)k * PAD_ROWS + dstrow] = accO[i][j] * inv;
        }
    }
}

// ===================== kernel: O projection (A+B cp.async, transposed A) =====================
// grid (33, 16). block 256. dyn smem SMEM_G.
__global__ __launch_bounds__(256, 2) void oproj_kernel(
    const float* __restrict__ Wo, float* __restrict__ out)
{
    extern __shared__ char smo[];
    const int rt = blockIdx.x, ct = blockIdx.y;
    const int tiles0 = (int)g_tiles0_dev;
    const int e = (rt < tiles0) ? 0 : 1;
    const int m0 = rt * 128, n0 = ct * 128;
    const float* W = Wo + (size_t)e * 2048 * 2048;

    const int tid = threadIdx.x;
    const int tx = tid & 15, ty = tid >> 4;

    float acc[8][8];
#pragma unroll
    for (int i = 0; i < 8; i++)
#pragma unroll
        for (int j = 0; j < 8; j++) acc[i][j] = 0.f;

    gemm_mainloop(smo, g_xT, m0, W, 2048, n0, tid, tx, ty, acc);

#pragma unroll
    for (int i = 0; i < 8; i++) {
        const int src = g_src[m0 + ty * 8 + i];
        if (src >= 0) {
            float* dst = &out[(size_t)src * 2048 + n0 + tx * 8];
            *(float4*)&dst[0] = make_float4(acc[i][0], acc[i][1], acc[i][2], acc[i][3]);
            *(float4*)&dst[4] = make_float4(acc[i][4], acc[i][5], acc[i][6], acc[i][7]);
        }
    }
}

// =====================================================================
extern "C" void kernel_launch(void* const* d_in, const int* in_sizes, int n_in,
                              void* d_out, int out_size)
{
    const float* hs   = (const float*)d_in[0];
    const int*   tt   = (const int*)  d_in[1];
    const float* cosp = (const float*)d_in[2];
    const float* sinp = (const float*)d_in[3];
    const float* Wq   = (const float*)d_in[4];
    const float* bq   = (const float*)d_in[5];
    const float* Wk   = (const float*)d_in[6];
    const float* bk   = (const float*)d_in[7];
    const float* Wv   = (const float*)d_in[8];
    const float* bv   = (const float*)d_in[9];
    const float* Wo   = (const float*)d_in[10];
    float* out = (float*)d_out;

    cudaFuncSetAttribute(attn_kernel,  cudaFuncAttributeMaxDynamicSharedMemorySize, 163840);
    cudaFuncSetAttribute(qkv_kernel,   cudaFuncAttributeMaxDynamicSharedMemorySize, SMEM_G);
    cudaFuncSetAttribute(oproj_kernel, cudaFuncAttributeMaxDynamicSharedMemorySize, SMEM_G);

    scan_kernel<<<1, 1024>>>(tt);
    gatherT_kernel<<<dim3(132, 64), dim3(32, 8)>>>(hs);
    qkv_kernel<<<dim3(33, 24), 256, SMEM_G>>>(Wq, bq, Wk, bk, Wv, bv, cosp, sinp);
    attn_kernel<<<dim3(16, 32), 256, 163840>>>();
    oproj_kernel<<<dim3(33, 16), 256, SMEM_G>>>(Wo, out);
}

// round 17
// speedup vs baseline: 1.2186x; 1.1321x over previous
#include <cuda_runtime.h>
#include <cstdint>
#include <math.h>

#define BB   2
#define SS   2048
#define HHID 2048
#define NHQ  16
#define NKVH 4
#define DDIM 128
#define TTOK (BB*SS)     // 4096
#define PAD_ROWS 4224    // 33 tiles of 128

// ---------------- scratch (~85MB, proven-safe envelope) ----------------
__device__ __align__(16) int g_src[PAD_ROWS];   // sorted row -> src token (-1 = pad)
__device__ __align__(16) int g_dst[TTOK];       // src token -> sorted row
__device__ unsigned g_tiles0_dev;
__device__ __align__(16) float g_q [(size_t)BB*NHQ *SS*DDIM];   // [B][NH][S][D]  (post-RoPE)
__device__ __align__(16) float g_k [(size_t)BB*NKVH*SS*DDIM];   // [B][NKV][S][D] (post-RoPE)
__device__ __align__(16) float g_v [(size_t)BB*NKVH*SS*DDIM];
// Transposed activation buffer, ALIASED:
//   phase 1 (gatherT -> qkv):   g_xT[k][m] = gathered hs (pads zero)
//   phase 2 (attn -> oproj):    g_xT[k][m] = attention output (sorted cols, pads stay zero)
__device__ __align__(16) float g_xT[(size_t)HHID*PAD_ROWS];

// ---------------- cp.async helpers ----------------
__device__ __forceinline__ uint32_t smem_u32(const void* p) {
    uint32_t a;
    asm("{ .reg .u64 t; cvta.to.shared.u64 t, %1; cvt.u32.u64 %0, t; }" : "=r"(a) : "l"(p));
    return a;
}
__device__ __forceinline__ void cp16(uint32_t d, const void* s) {
    uint64_t gs;
    asm("cvta.to.global.u64 %0, %1;" : "=l"(gs) : "l"(s));
    asm volatile("cp.async.cg.shared.global [%0], [%1], 16;" :: "r"(d), "l"(gs) : "memory");
}
#define CP_COMMIT() asm volatile("cp.async.commit_group;" ::: "memory")
#define CP_WAIT1()  asm volatile("cp.async.wait_group 1;" ::: "memory")
#define CP_WAIT0()  asm volatile("cp.async.wait_group 0;" ::: "memory")

// GEMM dyn smem: As[2][32][132] fp32, Bs[2][32][128] fp32
#define A_STG   16896
#define OFF_B   (2*A_STG)            // 33792
#define B_STG   16384
#define SMEM_G  (OFF_B + 2*B_STG)    // 66560

// Attention smem: sQ [128][132], sKP [128][132] (K then aliased P^T), sV [128][132]
#define AT_STR   132
#define AT_TILE  (128*AT_STR)        // floats: 16896
#define SMEM_A   (3*AT_TILE*4)       // 202752 bytes

// ===================== kernel: expert scan / permutation =====================
__global__ __launch_bounds__(1024) void scan_kernel(const int* __restrict__ tt)
{
    __shared__ int wtot[32];
    int tid = threadIdx.x, lane = tid & 31, wid = tid >> 5;
    for (int j = tid; j < PAD_ROWS; j += 1024) g_src[j] = -1;
    __syncthreads();

    int t0 = tid * 4;
    int cs[4];
#pragma unroll
    for (int i = 0; i < 4; i++) cs[i] = tt[t0 + i];
    int loc = cs[0] + cs[1] + cs[2] + cs[3];
    int inc = loc;
#pragma unroll
    for (int o = 1; o < 32; o <<= 1) { int v = __shfl_up_sync(0xffffffffu, inc, o); if (lane >= o) inc += v; }
    if (lane == 31) wtot[wid] = inc;
    __syncthreads();
    if (wid == 0) {
        int v = wtot[lane];
#pragma unroll
        for (int o = 1; o < 32; o <<= 1) { int u = __shfl_up_sync(0xffffffffu, v, o); if (lane >= o) v += u; }
        wtot[lane] = v;
    }
    __syncthreads();
    int total1 = wtot[31];
    int base1  = (wid > 0 ? wtot[wid - 1] : 0) + (inc - loc);
    int n0 = TTOK - total1;
    int tiles0 = (n0 + 127) >> 7;
    if (tid == 0) g_tiles0_dev = (unsigned)tiles0;
    int off1 = tiles0 * 128;
    int run1 = base1;
#pragma unroll
    for (int i = 0; i < 4; i++) {
        int idx = t0 + i;
        int dst = cs[i] ? (off1 + run1) : (idx - run1);
        g_dst[idx] = dst;
        g_src[dst] = idx;
        run1 += cs[i];
    }
}

// ===================== kernel: gather + transpose hs -> g_xT (pads zero) =====================
__global__ __launch_bounds__(256) void gatherT_kernel(const float* __restrict__ hs)
{
    __shared__ float t[32][33];
    const int m0 = blockIdx.x * 32, k0 = blockIdx.y * 32;
    const int tx = threadIdx.x, ty = threadIdx.y;
#pragma unroll
    for (int i = 0; i < 4; i++) {
        int r = ty + 8 * i;
        int src = g_src[m0 + r];
        t[r][tx] = (src >= 0) ? hs[(size_t)src * 2048 + k0 + tx] : 0.f;
    }
    __syncthreads();
#pragma unroll
    for (int i = 0; i < 4; i++) {
        int kk = ty + 8 * i;
        g_xT[(size_t)(k0 + kk) * PAD_ROWS + m0 + tx] = t[tx][kk];
    }
}

// ===================== GEMM (R16 proven: A+B cp.async double-buffered) =====================
__device__ __forceinline__ void issue_stage(uint32_t aBase, uint32_t bBase,
    const float* __restrict__ AT, int m0,
    const float* __restrict__ W, int nstr, int n0, int k0, int tid)
{
#pragma unroll
    for (int it = 0; it < 4; it++) {
        int id = tid + it * 256;
        int kr = id >> 5, g = id & 31;
        cp16(aBase + (uint32_t)(kr * 132 + g * 4) * 4,
             &AT[(size_t)(k0 + kr) * PAD_ROWS + m0 + g * 4]);
    }
#pragma unroll
    for (int it = 0; it < 4; it++) {
        int f = tid + it * 256;
        int kr = f >> 5, nc = f & 31;
        cp16(bBase + (uint32_t)(kr * 128 + nc * 4) * 4,
             &W[(size_t)(k0 + kr) * nstr + n0 + nc * 4]);
    }
    CP_COMMIT();
}

__device__ __forceinline__ void gemm_compute(
    const float (*As)[132], const float (*Bs)[128], int tx, int ty, float acc[8][8])
{
#pragma unroll 8
    for (int kk = 0; kk < 32; kk++) {
        float a[8], b[8];
        *(float4*)&a[0] = *(const float4*)&As[kk][ty * 8];
        *(float4*)&a[4] = *(const float4*)&As[kk][ty * 8 + 4];
        *(float4*)&b[0] = *(const float4*)&Bs[kk][tx * 8];
        *(float4*)&b[4] = *(const float4*)&Bs[kk][tx * 8 + 4];
#pragma unroll
        for (int i = 0; i < 8; i++)
#pragma unroll
            for (int j = 0; j < 8; j++)
                acc[i][j] = fmaf(a[i], b[j], acc[i][j]);
    }
}

__device__ __forceinline__ void gemm_mainloop(char* smem,
    const float* __restrict__ AT, int m0,
    const float* __restrict__ W, int nstr, int n0, int tid, int tx, int ty,
    float acc[8][8])
{
    uint32_t aBase = smem_u32(smem);
    uint32_t bBase = smem_u32(smem + OFF_B);

    issue_stage(aBase, bBase, AT, m0, W, nstr, n0, 0, tid);

    for (int s = 0; s < 64; s++) {
        __syncthreads();
        if (s + 1 < 64) {
            issue_stage(aBase + ((s + 1) & 1) * A_STG, bBase + ((s + 1) & 1) * B_STG,
                        AT, m0, W, nstr, n0, (s + 1) * 32, tid);
            CP_WAIT1();
        } else {
            CP_WAIT0();
        }
        __syncthreads();
        gemm_compute((const float(*)[132])(smem + (s & 1) * A_STG),
                     (const float(*)[128])(smem + OFF_B + (s & 1) * B_STG), tx, ty, acc);
    }
}

// ===================== kernel: QKV projection + bias + RoPE (R16 proven) =====================
__global__ __launch_bounds__(256, 2) void qkv_kernel(
    const float* __restrict__ Wq, const float* __restrict__ bq,
    const float* __restrict__ Wk, const float* __restrict__ bk,
    const float* __restrict__ Wv, const float* __restrict__ bv,
    const float* __restrict__ cosp, const float* __restrict__ sinp)
{
    extern __shared__ char smq[];
    const int rt = blockIdx.x, ct = blockIdx.y;
    const int tiles0 = (int)g_tiles0_dev;
    const int e = (rt < tiles0) ? 0 : 1;
    const int m0 = rt * 128;

    const float* W; const float* bias; int nstr, n0, which, head;
    if (ct < 16)      { W = Wq; bias = bq; nstr = 2048; n0 = ct * 128;        which = 0; head = ct;      }
    else if (ct < 20) { W = Wk; bias = bk; nstr = 512;  n0 = (ct - 16) * 128; which = 1; head = ct - 16; }
    else              { W = Wv; bias = bv; nstr = 512;  n0 = (ct - 20) * 128; which = 2; head = ct - 20; }
    W    += (size_t)e * 2048 * nstr;
    bias += (size_t)e * nstr;

    const int tid = threadIdx.x;
    const int tx = tid & 15, ty = tid >> 4;

    float acc[8][8];
#pragma unroll
    for (int i = 0; i < 8; i++)
#pragma unroll
        for (int j = 0; j < 8; j++) acc[i][j] = 0.f;

    gemm_mainloop(smq, g_xT, m0, W, nstr, n0, tid, tx, ty, acc);

    const float* bp = bias + n0;
#pragma unroll
    for (int i = 0; i < 8; i++) {
        const int row = m0 + ty * 8 + i;
        const int src = g_src[row];
        const int sEff = (src >= 0) ? src : 0;
        const int b = sEff >> 11, s = sEff & 2047;

        float v8[8];
#pragma unroll
        for (int j = 0; j < 8; j++) v8[j] = acc[i][j] + __ldg(&bp[tx * 8 + j]);

        if (which < 2) {
            float p8[8];
#pragma unroll
            for (int j = 0; j < 8; j++) p8[j] = __shfl_xor_sync(0xffffffffu, v8[j], 8);
            const size_t cb = ((size_t)(b * 2048 + s)) * 128;
#pragma unroll
            for (int j = 0; j < 8; j++) {
                int col = tx * 8 + j;
                float c  = __ldg(&cosp[cb + col]);
                float sn = __ldg(&sinp[cb + col]);
                v8[j] = (tx < 8) ? (v8[j] * c - p8[j] * sn)
                                 : (v8[j] * c + p8[j] * sn);
            }
        }

        if (src >= 0) {
            float* dst;
            if (which == 0)      dst = &g_q[((size_t)((b * NHQ  + head) * SS + s)) * DDIM + tx * 8];
            else if (which == 1) dst = &g_k[((size_t)((b * NKVH + head) * SS + s)) * DDIM + tx * 8];
            else                 dst = &g_v[((size_t)((b * NKVH + head) * SS + s)) * DDIM + tx * 8];
            *(float4*)&dst[0] = make_float4(v8[0], v8[1], v8[2], v8[3]);
            *(float4*)&dst[4] = make_float4(v8[4], v8[5], v8[6], v8[7]);
        }
    }
}

// ===================== kernel: causal flash attention — natural layouts, BKV=128, aliased P^T =====================
// grid: (16 q-tiles [reversed], B*NH=32). block 256 (tx 16, ty 16). smem 202752.
__global__ __launch_bounds__(256) void attn_kernel()
{
    extern __shared__ float sm[];
    float* sQ  = sm;                 // [128 r][132]
    float* sKP = sm + AT_TILE;       // [128 c][132]  K tile, then aliased P^T [c][132->rows]
    float* sV  = sm + 2 * AT_TILE;   // [128 c][132]

    const int bh = blockIdx.y;
    const int b = bh >> 4, h = bh & 15, hk = h >> 2;
    const int qt = 15 - blockIdx.x;
    const int q0 = qt * 128;
    const float* Q = g_q + (size_t)(b * NHQ  + h ) * SS * DDIM;
    const float* K = g_k + (size_t)(b * NKVH + hk) * SS * DDIM;
    const float* V = g_v + (size_t)(b * NKVH + hk) * SS * DDIM;

    const int tid = threadIdx.x;
    const int tx = tid & 15, ty = tid >> 4;

    // ---- load Q tile (natural, vectorized, conflict-free) ----
#pragma unroll
    for (int it = 0; it < 16; it++) {
        int f = tid + it * 256;
        int r = f >> 5, dc = f & 31;
        *(float4*)&sQ[r * AT_STR + dc * 4] = *(const float4*)&Q[(size_t)(q0 + r) * DDIM + dc * 4];
    }

    float accO[8][8];
    float mrow[8], lrow[8];
#pragma unroll
    for (int i = 0; i < 8; i++) {
        mrow[i] = -1e30f; lrow[i] = 0.f;
#pragma unroll
        for (int j = 0; j < 8; j++) accO[i][j] = 0.f;
    }

    const float scale = 0.08838834764831845f;
    const int ktiles = qt + 1;     // BKV = 128

    for (int kt = 0; kt < ktiles; kt++) {
        const int k0 = kt * 128;
        __syncthreads();           // prior PV done reading sKP(P)/sV
        // ---- load K,V tiles (natural) ----
#pragma unroll
        for (int it = 0; it < 16; it++) {
            int f = tid + it * 256;
            int c = f >> 5, dc = f & 31;
            *(float4*)&sKP[c * AT_STR + dc * 4] = *(const float4*)&K[(size_t)(k0 + c) * DDIM + dc * 4];
            *(float4*)&sV [c * AT_STR + dc * 4] = *(const float4*)&V[(size_t)(k0 + c) * DDIM + dc * 4];
        }
        __syncthreads();

        // ---- S = Q K^T via d-grouped float4 dots; cols = tx + 16*j ----
        float sc[8][8];
#pragma unroll
        for (int i = 0; i < 8; i++)
#pragma unroll
            for (int j = 0; j < 8; j++) sc[i][j] = 0.f;
#pragma unroll 4
        for (int dg = 0; dg < 32; dg++) {
            float4 q4[8], k4[8];
#pragma unroll
            for (int i = 0; i < 8; i++) q4[i] = *(const float4*)&sQ[(ty * 8 + i) * AT_STR + dg * 4];
#pragma unroll
            for (int j = 0; j < 8; j++) k4[j] = *(const float4*)&sKP[(tx + 16 * j) * AT_STR + dg * 4];
#pragma unroll
            for (int i = 0; i < 8; i++)
#pragma unroll
                for (int j = 0; j < 8; j++) {
                    sc[i][j] = fmaf(q4[i].x, k4[j].x, sc[i][j]);
                    sc[i][j] = fmaf(q4[i].y, k4[j].y, sc[i][j]);
                    sc[i][j] = fmaf(q4[i].z, k4[j].z, sc[i][j]);
                    sc[i][j] = fmaf(q4[i].w, k4[j].w, sc[i][j]);
                }
        }
        // ---- scale + causal mask ----
#pragma unroll
        for (int i = 0; i < 8; i++)
#pragma unroll
            for (int j = 0; j < 8; j++) sc[i][j] *= scale;
        if (k0 + 127 > q0) {
#pragma unroll
            for (int i = 0; i < 8; i++)
#pragma unroll
                for (int j = 0; j < 8; j++)
                    if (k0 + tx + 16 * j > q0 + ty * 8 + i) sc[i][j] = -1e30f;
        }
        // ---- online softmax ----
#pragma unroll
        for (int i = 0; i < 8; i++) {
            float mx = sc[i][0];
#pragma unroll
            for (int j = 1; j < 8; j++) mx = fmaxf(mx, sc[i][j]);
#pragma unroll
            for (int o = 1; o < 16; o <<= 1) mx = fmaxf(mx, __shfl_xor_sync(0xffffffffu, mx, o));
            float mn = fmaxf(mrow[i], mx);
            float alpha = __expf(mrow[i] - mn);
            mrow[i] = mn;
            float rs = 0.f;
#pragma unroll
            for (int j = 0; j < 8; j++) { float p = __expf(sc[i][j] - mn); sc[i][j] = p; rs += p; }
#pragma unroll
            for (int o = 1; o < 16; o <<= 1) rs += __shfl_xor_sync(0xffffffffu, rs, o);
            lrow[i] = lrow[i] * alpha + rs;
#pragma unroll
            for (int j = 0; j < 8; j++) accO[i][j] *= alpha;
        }
        // ---- stage P^T into aliased K buffer ----
        __syncthreads();           // all QK reads of sKP done
#pragma unroll
        for (int i = 0; i < 8; i++)
#pragma unroll
            for (int j = 0; j < 8; j++)
                sKP[(tx + 16 * j) * AT_STR + ty * 8 + i] = sc[i][j];
        __syncthreads();
        // ---- O += P V ----
#pragma unroll 4
        for (int c = 0; c < 128; c++) {
            float pf[8], vf[8];
            *(float4*)&pf[0] = *(const float4*)&sKP[c * AT_STR + ty * 8];
            *(float4*)&pf[4] = *(const float4*)&sKP[c * AT_STR + ty * 8 + 4];
            *(float4*)&vf[0] = *(const float4*)&sV[c * AT_STR + tx * 8];
            *(float4*)&vf[4] = *(const float4*)&sV[c * AT_STR + tx * 8 + 4];
#pragma unroll
            for (int i = 0; i < 8; i++)
#pragma unroll
                for (int j = 0; j < 8; j++)
                    accO[i][j] = fmaf(pf[i], vf[j], accO[i][j]);
        }
    }

    // ---- epilogue: normalize, write TRANSPOSED into g_xT[k][sorted_row] ----
#pragma unroll
    for (int i = 0; i < 8; i++) {
        float inv = 1.f / lrow[i];
        int srow = q0 + ty * 8 + i;
        int dstrow = g_dst[b * 2048 + srow];
#pragma unroll
        for (int j = 0; j < 8; j++) {
            int k = h * DDIM + tx * 8 + j;
            g_xT[(size_t)k * PAD_ROWS + dstrow] = accO[i][j] * inv;
        }
    }
}

// ===================== kernel: O projection (R16 proven) =====================
__global__ __launch_bounds__(256, 2) void oproj_kernel(
    const float* __restrict__ Wo, float* __restrict__ out)
{
    extern __shared__ char smo[];
    const int rt = blockIdx.x, ct = blockIdx.y;
    const int tiles0 = (int)g_tiles0_dev;
    const int e = (rt < tiles0) ? 0 : 1;
    const int m0 = rt * 128, n0 = ct * 128;
    const float* W = Wo + (size_t)e * 2048 * 2048;

    const int tid = threadIdx.x;
    const int tx = tid & 15, ty = tid >> 4;

    float acc[8][8];
#pragma unroll
    for (int i = 0; i < 8; i++)
#pragma unroll
        for (int j = 0; j < 8; j++) acc[i][j] = 0.f;

    gemm_mainloop(smo, g_xT, m0, W, 2048, n0, tid, tx, ty, acc);

#pragma unroll
    for (int i = 0; i < 8; i++) {
        const int src = g_src[m0 + ty * 8 + i];
        if (src >= 0) {
            float* dst = &out[(size_t)src * 2048 + n0 + tx * 8];
            *(float4*)&dst[0] = make_float4(acc[i][0], acc[i][1], acc[i][2], acc[i][3]);
            *(float4*)&dst[4] = make_float4(acc[i][4], acc[i][5], acc[i][6], acc[i][7]);
        }
    }
}

// =====================================================================
extern "C" void kernel_launch(void* const* d_in, const int* in_sizes, int n_in,
                              void* d_out, int out_size)
{
    const float* hs   = (const float*)d_in[0];
    const int*   tt   = (const int*)  d_in[1];
    const float* cosp = (const float*)d_in[2];
    const float* sinp = (const float*)d_in[3];
    const float* Wq   = (const float*)d_in[4];
    const float* bq   = (const float*)d_in[5];
    const float* Wk   = (const float*)d_in[6];
    const float* bk   = (const float*)d_in[7];
    const float* Wv   = (const float*)d_in[8];
    const float* bv   = (const float*)d_in[9];
    const float* Wo   = (const float*)d_in[10];
    float* out = (float*)d_out;

    cudaFuncSetAttribute(attn_kernel,  cudaFuncAttributeMaxDynamicSharedMemorySize, SMEM_A);
    cudaFuncSetAttribute(qkv_kernel,   cudaFuncAttributeMaxDynamicSharedMemorySize, SMEM_G);
    cudaFuncSetAttribute(oproj_kernel, cudaFuncAttributeMaxDynamicSharedMemorySize, SMEM_G);

    scan_kernel<<<1, 1024>>>(tt);
    gatherT_kernel<<<dim3(132, 64), dim3(32, 8)>>>(hs);
    qkv_kernel<<<dim3(33, 24), 256, SMEM_G>>>(Wq, bq, Wk, bk, Wv, bv, cosp, sinp);
    attn_kernel<<<dim3(16, 32), 256, SMEM_A>>>();
    oproj_kernel<<<dim3(33, 16), 256, SMEM_G>>>(Wo, out);
}